// round 8
// baseline (speedup 1.0000x reference)
#include <cuda_runtime.h>
#include <math.h>

#define BB   8
#define NN   1024
#define KK   32
#define DD   256
#define HH   8
#define DHH  32
#define TD   16
#define NBB  32
#define HIDD 128
#define SHDD 9

// ---------------- scratch (device globals; no allocations allowed) ----------------
__device__ int   g_knn  [BB*NN*KK];
__device__ float g_rbf  [BB*NN*KK*NBB];      // rbf * cut, per edge
__device__ float g_cut  [BB*NN*KK];
__device__ float g_sh   [BB*NN*KK*SHDD];
__device__ float g_node [2][BB*NN*DD];       // ping-pong node features
__device__ float g_P1   [BB*NN*HIDD];        // node[:, :128] @ Wk1[48:176]
__device__ float g_P2   [BB*NN*HIDD];        // node[:, :128] @ Wk1[176:304] + bias + t-part
__device__ float g_m    [BB*NN*HIDD*HH];     // m[j][h] = sum_d Wk2[j, h*32+d] * q[h*32+d]
__device__ float g_vsrc [BB*NN*DD];          // node @ Wv[0:256]
__device__ float g_agg  [BB*NN*DD];
__device__ float g_logit[BB*NN*KK*HH];       // attention logits per edge/head

// fast, accurate tanh: sign(x)*(1-e^-2|x|)/(1+e^-2|x|); __expf rel err ~1e-7
__device__ __forceinline__ float tanh_f(float x) {
    float ax = fabsf(x);
    float t  = __expf(-2.f * ax);
    float r  = (1.f - t) / (1.f + t);
    return copysignf(r, x);
}

__device__ __forceinline__ float gelu_t(float x) {
    // matches jax.nn.gelu (approximate=True, tanh form)
    float x3 = x * x * x;
    return 0.5f * x * (1.f + tanh_f(0.7978845608028654f * (x + 0.044715f * x3)));
}

__device__ __forceinline__ unsigned long long umin64(unsigned long long a, unsigned long long b) {
    return a < b ? a : b;
}

// ---------------- kNN: per-node top-32 smallest d2 (self included) ----------------
__global__ void __launch_bounds__(256) k_knn(const float* __restrict__ x) {
    int bn = blockIdx.x;
    int b = bn >> 10, n = bn & 1023;
    const float* pos = x + (size_t)b * NN * 3;
    float px = pos[n*3+0], py = pos[n*3+1], pz = pos[n*3+2];
    int tid = threadIdx.x;
    unsigned long long key[4];
#pragma unroll
    for (int m = 0; m < 4; m++) {
        int j = tid + m * 256;
        float dx = px - pos[j*3+0];
        float dy = py - pos[j*3+1];
        float dz = pz - pos[j*3+2];
        float d2 = dx*dx + dy*dy + dz*dz;   // >= 0 -> float bits are order-preserving
        key[m] = ((unsigned long long)__float_as_uint(d2) << 32) | (unsigned int)j;
    }
    __shared__ unsigned long long s_w[8];
    __shared__ unsigned long long s_best;
    int lane = tid & 31, wp = tid >> 5;
    for (int it = 0; it < KK; it++) {
        unsigned long long bm = umin64(umin64(key[0], key[1]), umin64(key[2], key[3]));
#pragma unroll
        for (int off = 16; off > 0; off >>= 1)
            bm = umin64(bm, __shfl_xor_sync(0xffffffffu, bm, off));
        if (lane == 0) s_w[wp] = bm;
        __syncthreads();
        if (tid == 0) {
            unsigned long long bb = s_w[0];
#pragma unroll
            for (int w = 1; w < 8; w++) bb = umin64(bb, s_w[w]);
            s_best = bb;
            g_knn[(size_t)bn * KK + it] = (int)(bb & 0xffffffffULL);
        }
        __syncthreads();
        unsigned long long bb = s_best;
#pragma unroll
        for (int m = 0; m < 4; m++)
            if (key[m] == bb) key[m] = 0xffffffffffffffffULL;
    }
}

// ---------------- per-edge geometry: sh, cut, rbf*cut ----------------
__global__ void __launch_bounds__(256) k_edges(const float* __restrict__ x) {
    int e = blockIdx.x * 256 + threadIdx.x;          // < BB*NN*KK = 262144
    int b  = e >> 15;                                 // NN*KK = 32768
    int nk = e & 32767;
    int n  = nk >> 5;
    int src = g_knn[e];
    const float* pos = x + (size_t)b * NN * 3;
    float vx = pos[n*3+0] - pos[src*3+0];
    float vy = pos[n*3+1] - pos[src*3+1];
    float vz = pos[n*3+2] - pos[src*3+2];
    float r = sqrtf(vx*vx + vy*vy + vz*vz);
    float inv = 1.f / fmaxf(r, 1e-9f);
    float ux = vx*inv, uy = vy*inv, uz = vz*inv;
    const float S3  = 1.7320508075688772f;
    const float S15 = 3.872983346207417f;
    const float S5  = 2.23606797749979f;
    float sh[9];
    sh[0] = 1.f;
    sh[1] = S3 * ux; sh[2] = S3 * uy; sh[3] = S3 * uz;
    sh[4] = S15 * ux * uy;
    sh[5] = S15 * uy * uz;
    sh[6] = 0.5f * S5 * (3.f * uz * uz - 1.f);
    sh[7] = S15 * ux * uz;
    sh[8] = 0.5f * S15 * (ux*ux - uy*uy);
#pragma unroll
    for (int s = 0; s < 9; s++) g_sh[(size_t)e * SHDD + s] = sh[s];
    float xx = 10.f * (1.f - 0.5f * r);
    float cut = (xx > 0.f) ? 1.4f * __expf(-1.f / xx) : 0.f;
    g_cut[e] = cut;
    const float step = 2.0f / 31.0f;
    const float fact = 4.7982245866230005f;   // sqrt(32)*0.95/1.12
    float fc = fact * cut;
    float rs = r / step;
#pragma unroll
    for (int i = 0; i < NBB; i++) {
        float d = rs - (float)i;
        g_rbf[(size_t)e * NBB + i] = __expf(-d*d) * fc;
    }
}

// ---------------- node embedding: [y, t] @ W_embed ----------------
__global__ void __launch_bounds__(256) k_embed(const float* __restrict__ y,
                                               const float* __restrict__ t,
                                               const float* __restrict__ W) {
    __shared__ float s_in[19];
    int bn = blockIdx.x, b = bn >> 10, tid = threadIdx.x;
    if (tid < 3) s_in[tid] = y[(size_t)bn * 3 + tid];
    else if (tid < 19) s_in[tid] = t[b * TD + tid - 3];
    __syncthreads();
    float acc = 0.f;
#pragma unroll
    for (int i = 0; i < 19; i++) acc += s_in[i] * W[i * DD + tid];
    g_node[0][(size_t)bn * DD + tid] = acc;
}

// ---------------- per-layer precompute: q->m, vsrc, P1, P2 (16-node tiles) ----------------
__global__ void __launch_bounds__(256, 3) k_pre(int cur,
        const float* __restrict__ Wq, const float* __restrict__ Wv,
        const float* __restrict__ Wk1, const float* __restrict__ Wk2,
        const float* __restrict__ bk1, const float* __restrict__ t) {
    __shared__ float s_nd[16 * DD];
    __shared__ float s_q [16 * DD];
    int tid = threadIdx.x;
    int node0 = blockIdx.x * 16;
    int b = node0 >> 10;
    const float* nodein = g_node[cur];
    const float* np = nodein + (size_t)node0 * DD;
    for (int i = tid; i < 16 * DD; i += 256) s_nd[i] = np[i];
    __syncthreads();

    // q (column tid), 16 accumulators
    {
        float acc[16];
#pragma unroll
        for (int g = 0; g < 16; g++) acc[g] = 0.f;
        for (int i = 0; i < DD; i += 4) {
            float q0 = Wq[(i+0)*DD + tid], q1 = Wq[(i+1)*DD + tid];
            float q2 = Wq[(i+2)*DD + tid], q3 = Wq[(i+3)*DD + tid];
#pragma unroll
            for (int g = 0; g < 16; g++) {
                float4 a = *(const float4*)&s_nd[g*DD + i];
                acc[g] += a.x*q0 + a.y*q1 + a.z*q2 + a.w*q3;
            }
        }
#pragma unroll
        for (int g = 0; g < 16; g++) s_q[g*DD + tid] = acc[g];
    }
    // vsrc (column tid)
    {
        float acc[16];
#pragma unroll
        for (int g = 0; g < 16; g++) acc[g] = 0.f;
        for (int i = 0; i < DD; i += 4) {
            float v0 = Wv[(i+0)*DD + tid], v1 = Wv[(i+1)*DD + tid];
            float v2 = Wv[(i+2)*DD + tid], v3 = Wv[(i+3)*DD + tid];
#pragma unroll
            for (int g = 0; g < 16; g++) {
                float4 a = *(const float4*)&s_nd[g*DD + i];
                acc[g] += a.x*v0 + a.y*v1 + a.z*v2 + a.w*v3;
            }
        }
#pragma unroll
        for (int g = 0; g < 16; g++)
            g_vsrc[(size_t)(node0 + g) * DD + tid] = acc[g];
    }

    // P1 (threads 0..127) / P2 (threads 128..255)
    {
        float acc[16];
#pragma unroll
        for (int g = 0; g < 16; g++) acc[g] = 0.f;
        int j = tid & 127;
        int rowbase = (tid < 128) ? 48 : 176;
        const float* W = Wk1 + rowbase * HIDD + j;
        for (int i = 0; i < 128; i += 4) {
            float w0 = W[(i+0)*HIDD], w1 = W[(i+1)*HIDD];
            float w2 = W[(i+2)*HIDD], w3 = W[(i+3)*HIDD];
#pragma unroll
            for (int g = 0; g < 16; g++) {
                float4 a = *(const float4*)&s_nd[g*DD + i];
                acc[g] += a.x*w0 + a.y*w1 + a.z*w2 + a.w*w3;
            }
        }
        if (tid < 128) {
#pragma unroll
            for (int g = 0; g < 16; g++)
                g_P1[(size_t)(node0 + g) * HIDD + j] = acc[g];
        } else {
            float base = bk1[j];
#pragma unroll
            for (int ii = 0; ii < TD; ii++)
                base += t[b * TD + ii] * Wk1[(NBB + ii) * HIDD + j];
#pragma unroll
            for (int g = 0; g < 16; g++)
                g_P2[(size_t)(node0 + g) * HIDD + j] = acc[g] + base;
        }
    }
    __syncthreads();

    // m[j][hh] = sum_d Wk2[j, hh*32+d] * q[hh*32+d]
    {
        int j  = tid & 127;
        int hb = (tid >> 7) * 4;
        for (int hh = hb; hh < hb + 4; hh++) {
            const float* W = Wk2 + j * DD + hh * DHH;
            float4 w[8];
#pragma unroll
            for (int d8 = 0; d8 < 8; d8++) w[d8] = *(const float4*)&W[d8 * 4];
#pragma unroll
            for (int g = 0; g < 16; g++) {
                float s = 0.f;
#pragma unroll
                for (int d8 = 0; d8 < 8; d8++) {
                    float4 q = *(const float4*)&s_q[g*DD + hh*DHH + d8*4];
                    s += w[d8].x*q.x + w[d8].y*q.y + w[d8].z*q.z + w[d8].w*q.w;
                }
                g_m[((size_t)(node0 + g) * HIDD + j) * HH + hh] = s;
            }
        }
    }
}

// ---------------- edge MLP h + logits (2 nodes = 64 edges per block) ----------------
// h[e][j] = gelu(rbf[e]@Wk1[0:32] + P1[src_e] + P2[dst_e]); logits[e][hh] = h[e].m[dst_e][:,hh]/sqrt(32)
__global__ void __launch_bounds__(256, 4) k_h(const float* __restrict__ Wk1l) {
    __shared__ float s_h[64 * HIDD];    // 32KB; first 8KB aliases rbf staging
    __shared__ float s_m2[2 * HIDD * HH]; // 8KB
    __shared__ int   s_src[64];
    float* s_rbf = s_h;                 // [64][32] (consumed before h is written)

    int tid = threadIdx.x;
    int node0 = blockIdx.x * 2;
    int b = node0 >> 10;
    size_t ebase = (size_t)node0 * KK;  // 64 edges

    for (int i = tid; i < 64 * NBB; i += 256) s_rbf[i] = g_rbf[ebase * NBB + i];
    for (int i = tid; i < 2 * HIDD * HH; i += 256) s_m2[i] = g_m[(size_t)node0 * (HIDD*HH) + i];
    if (tid < 64) s_src[tid] = g_knn[ebase + tid];
    __syncthreads();

    int j = tid & 127, eh = tid >> 7;   // eh in {0,1} -> node
    float acc[32];
#pragma unroll
    for (int e = 0; e < 32; e++) acc[e] = 0.f;
#pragma unroll
    for (int i = 0; i < NBB; i += 4) {
        float w0 = Wk1l[(i+0)*HIDD + j], w1 = Wk1l[(i+1)*HIDD + j];
        float w2 = Wk1l[(i+2)*HIDD + j], w3 = Wk1l[(i+3)*HIDD + j];
#pragma unroll
        for (int e = 0; e < 32; e++) {
            float4 rb = *(const float4*)&s_rbf[(eh*32 + e)*NBB + i];
            acc[e] += rb.x*w0 + rb.y*w1 + rb.z*w2 + rb.w*w3;
        }
    }
    float p2 = g_P2[(size_t)(node0 + eh) * HIDD + j];
    const float* p1base = g_P1 + (size_t)(b * NN) * HIDD + j;
    __syncthreads();   // all rbf reads done before aliased h writes
#pragma unroll
    for (int e0 = 0; e0 < 32; e0 += 8) {
        float p1v[8];
#pragma unroll
        for (int u = 0; u < 8; u++)
            p1v[u] = __ldg(&p1base[(size_t)s_src[eh*32 + e0 + u] * HIDD]);
#pragma unroll
        for (int u = 0; u < 8; u++)
            s_h[(eh*32 + e0 + u)*HIDD + j] = gelu_t(acc[e0 + u] + p1v[u] + p2);
    }
    __syncthreads();

    // logits: 512 outputs (64 edges x 8 heads), 2 per thread
#pragma unroll
    for (int rep = 0; rep < 2; rep++) {
        int o = tid + rep * 256;
        int e = o >> 3, hh = o & 7, nd = e >> 5;
        const float* mm = &s_m2[nd * (HIDD*HH) + hh];
        float s = 0.f;
#pragma unroll 8
        for (int jj = 0; jj < HIDD; jj += 4) {
            float4 hv = *(const float4*)&s_h[e*HIDD + jj];
            s += hv.x*mm[(jj+0)*8] + hv.y*mm[(jj+1)*8]
               + hv.z*mm[(jj+2)*8] + hv.w*mm[(jj+3)*8];
        }
        g_logit[(ebase + e)*HH + hh] = s * 0.17677669529663687f;
    }
}

// ---------------- softmax + sh-contraction + gather-aggregate (1 node / block) ----------------
__global__ void __launch_bounds__(256) k_attn(const float* __restrict__ Wvl) {
    __shared__ float s_alpha[KK * HH];   // [k][hh]
    __shared__ float s_zsh[HH * SHDD];
    __shared__ float s_sh[KK * SHDD];
    __shared__ int   s_src[KK];

    int bn = blockIdx.x, b = bn >> 10, tid = threadIdx.x;
    int wp = tid >> 5, lane = tid & 31;  // wp = head, lane = k
    size_t ebase = (size_t)bn * KK;

    if (tid < KK) s_src[tid] = g_knn[ebase + tid];
    for (int i = tid; i < KK * SHDD; i += 256) s_sh[i] = g_sh[ebase * SHDD + i];

    float lg  = g_logit[(ebase + lane) * HH + wp];
    float cut = g_cut[ebase + lane];
    float mx = lg;
#pragma unroll
    for (int off = 16; off > 0; off >>= 1)
        mx = fmaxf(mx, __shfl_xor_sync(0xffffffffu, mx, off));
    float w = cut * __expf(lg - mx);
    float sum = w;
#pragma unroll
    for (int off = 16; off > 0; off >>= 1)
        sum += __shfl_xor_sync(0xffffffffu, sum, off);
    float alpha = w / (sum + 1e-9f);
    s_alpha[lane * HH + wp] = alpha;
    __syncthreads();

    // zsh[hh][s] = sum_k alpha * sh  (warp per head, shuffle reduce)
#pragma unroll
    for (int s = 0; s < SHDD; s++) {
        float v = alpha * s_sh[lane * SHDD + s];
#pragma unroll
        for (int off = 16; off > 0; off >>= 1)
            v += __shfl_xor_sync(0xffffffffu, v, off);
        if (lane == 0) s_zsh[wp * SHDD + s] = v;
    }
    __syncthreads();

    // agg[c] = sum_k alpha*vsrc[src] + sum_s zsh*Wv[256+s]
    {
        int c = tid, hh = tid >> 5;
        const float* vb = g_vsrc + (size_t)(b * NN) * DD;
        float a0 = 0.f, a1 = 0.f, a2 = 0.f, a3 = 0.f;
#pragma unroll
        for (int k = 0; k < KK; k += 4) {
            a0 += s_alpha[(k+0)*HH + hh] * __ldg(&vb[(size_t)s_src[k+0]*DD + c]);
            a1 += s_alpha[(k+1)*HH + hh] * __ldg(&vb[(size_t)s_src[k+1]*DD + c]);
            a2 += s_alpha[(k+2)*HH + hh] * __ldg(&vb[(size_t)s_src[k+2]*DD + c]);
            a3 += s_alpha[(k+3)*HH + hh] * __ldg(&vb[(size_t)s_src[k+3]*DD + c]);
        }
        float acc = (a0 + a1) + (a2 + a3);
#pragma unroll
        for (int s = 0; s < SHDD; s++)
            acc += s_zsh[hh * SHDD + s] * Wvl[(256 + s) * DD + c];
        g_agg[(size_t)bn * DD + c] = acc;
    }
}

// ---------------- output projection + scalar activation (layers 0..2) ----------------
__global__ void __launch_bounds__(256, 3) k_proj(int cur, const float* __restrict__ Wo) {
    __shared__ float s_agg[16 * DD];
    int tid = threadIdx.x;
    int node0 = blockIdx.x * 16;
    const float* nodein = g_node[cur];
    float* nodeout = g_node[cur ^ 1];
    const float* ap = g_agg + (size_t)node0 * DD;
    for (int i = tid; i < 16 * DD; i += 256) s_agg[i] = ap[i];
    __syncthreads();
    float acc[16];
#pragma unroll
    for (int g = 0; g < 16; g++) acc[g] = 0.f;
    for (int i = 0; i < DD; i += 4) {
        float w0 = Wo[(i+0)*DD + tid], w1 = Wo[(i+1)*DD + tid];
        float w2 = Wo[(i+2)*DD + tid], w3 = Wo[(i+3)*DD + tid];
#pragma unroll
        for (int g = 0; g < 16; g++) {
            float4 a = *(const float4*)&s_agg[g*DD + i];
            acc[g] += a.x*w0 + a.y*w1 + a.z*w2 + a.w*w3;
        }
    }
#pragma unroll
    for (int g = 0; g < 16; g++) {
        float v = nodein[(size_t)(node0 + g) * DD + tid] + acc[g];
        if (tid < 64)       v = gelu_t(v);
        else if (tid < 128) v = tanh_f(v);
        nodeout[(size_t)(node0 + g) * DD + tid] = v;
    }
}

// ---------------- final projection agg @ Wo_out -> [B,N,3] ----------------
__global__ void __launch_bounds__(256) k_final(const float* __restrict__ Wo_out,
                                               float* __restrict__ out) {
    int gid = blockIdx.x * 256 + threadIdx.x;
    if (gid >= BB * NN * 3) return;
    int n = gid / 3, c = gid - n * 3;
    const float* ap = g_agg + (size_t)n * DD;
    float acc = 0.f;
#pragma unroll 4
    for (int i = 0; i < DD; i++) acc += ap[i] * Wo_out[i * 3 + c];
    out[gid] = acc;
}

// ---------------- launch ----------------
extern "C" void kernel_launch(void* const* d_in, const int* in_sizes, int n_in,
                              void* d_out, int out_size) {
    const float* x       = (const float*)d_in[0];
    const float* y       = (const float*)d_in[1];
    const float* t       = (const float*)d_in[2];
    const float* W_embed = (const float*)d_in[3];
    const float* Wk1     = (const float*)d_in[4];
    const float* bk1     = (const float*)d_in[5];
    const float* Wk2     = (const float*)d_in[6];
    const float* Wq      = (const float*)d_in[7];
    const float* Wv      = (const float*)d_in[8];
    const float* Wo      = (const float*)d_in[9];
    const float* Wo_out  = (const float*)d_in[10];
    float* out = (float*)d_out;

    k_knn  <<<BB*NN, 256>>>(x);
    k_edges<<<BB*NN*KK/256, 256>>>(x);
    k_embed<<<BB*NN, 256>>>(y, t, W_embed);

    for (int l = 0; l < 4; l++) {
        int cur = l & 1;
        const float* Wk1l = Wk1 + (size_t)l * 304 * HIDD;
        const float* Wvl  = Wv  + (size_t)l * 265 * DD;
        k_pre<<<BB*NN/16, 256>>>(cur,
                                 Wq + (size_t)l * DD * DD,
                                 Wvl, Wk1l,
                                 Wk2 + (size_t)l * HIDD * DD,
                                 bk1 + (size_t)l * HIDD,
                                 t);
        k_h   <<<BB*NN/2, 256>>>(Wk1l);
        k_attn<<<BB*NN, 256>>>(Wvl);
        if (l < 3) k_proj<<<BB*NN/16, 256>>>(cur, Wo + (size_t)l * DD * DD);
    }
    k_final<<<(BB*NN*3 + 255)/256, 256>>>(Wo_out, out);
}

// round 13
// speedup vs baseline: 1.7770x; 1.7770x over previous
#include <cuda_runtime.h>
#include <math.h>

#define BB   8
#define NN   1024
#define KK   32
#define DD   256
#define HH   8
#define DHH  32
#define TD   16
#define NBB  32
#define HIDD 128
#define SHDD 9

// ---------------- scratch (device globals; no allocations allowed) ----------------
__device__ int   g_knn  [BB*NN*KK];
__device__ float g_rbf  [BB*NN*KK*NBB];      // rbf * cut, per edge
__device__ float g_cut  [BB*NN*KK];
__device__ float g_sh   [BB*NN*KK*SHDD];
__device__ float g_node [2][BB*NN*DD];       // ping-pong node features
__device__ float g_P1   [BB*NN*HIDD];        // node[:, :128] @ Wk1[48:176]
__device__ float g_P2   [BB*NN*HIDD];        // node[:, :128] @ Wk1[176:304] + bias + t-part
__device__ float g_m    [BB*NN*HIDD*HH];     // m[n][j][h] = sum_d Wk2[j, h*32+d] * q[n, h*32+d]
__device__ float g_vsrc [BB*NN*DD];          // node @ Wv[0:256]
__device__ float g_agg  [BB*NN*DD];
__device__ float g_logit[BB*NN*KK*HH];       // attention logits per edge/head

// fast, accurate tanh: sign(x)*(1-e^-2|x|)/(1+e^-2|x|); __expf rel err ~1e-7
__device__ __forceinline__ float tanh_f(float x) {
    float ax = fabsf(x);
    float t  = __expf(-2.f * ax);
    float r  = (1.f - t) / (1.f + t);
    return copysignf(r, x);
}

// gelu (tanh form) via sigmoid identity: 0.5*(1+tanh(z)) = 1/(1+exp(-2z))
__device__ __forceinline__ float gelu_t(float x) {
    float z = 0.7978845608028654f * (x + 0.044715f * x * x * x);
    return __fdividef(x, 1.f + __expf(-2.f * z));
}

__device__ __forceinline__ unsigned long long umin64(unsigned long long a, unsigned long long b) {
    return a < b ? a : b;
}

// ---------------- kNN: per-node top-32 smallest d2 (self included) ----------------
__global__ void __launch_bounds__(256) k_knn(const float* __restrict__ x) {
    int bn = blockIdx.x;
    int b = bn >> 10, n = bn & 1023;
    const float* pos = x + (size_t)b * NN * 3;
    float px = pos[n*3+0], py = pos[n*3+1], pz = pos[n*3+2];
    int tid = threadIdx.x;
    unsigned long long key[4];
#pragma unroll
    for (int m = 0; m < 4; m++) {
        int j = tid + m * 256;
        float dx = px - pos[j*3+0];
        float dy = py - pos[j*3+1];
        float dz = pz - pos[j*3+2];
        float d2 = dx*dx + dy*dy + dz*dz;   // >= 0 -> float bits are order-preserving
        key[m] = ((unsigned long long)__float_as_uint(d2) << 32) | (unsigned int)j;
    }
    __shared__ unsigned long long s_w[8];
    __shared__ unsigned long long s_best;
    int lane = tid & 31, wp = tid >> 5;
    for (int it = 0; it < KK; it++) {
        unsigned long long bm = umin64(umin64(key[0], key[1]), umin64(key[2], key[3]));
#pragma unroll
        for (int off = 16; off > 0; off >>= 1)
            bm = umin64(bm, __shfl_xor_sync(0xffffffffu, bm, off));
        if (lane == 0) s_w[wp] = bm;
        __syncthreads();
        if (tid == 0) {
            unsigned long long bb = s_w[0];
#pragma unroll
            for (int w = 1; w < 8; w++) bb = umin64(bb, s_w[w]);
            s_best = bb;
            g_knn[(size_t)bn * KK + it] = (int)(bb & 0xffffffffULL);
        }
        __syncthreads();
        unsigned long long bb = s_best;
#pragma unroll
        for (int m = 0; m < 4; m++)
            if (key[m] == bb) key[m] = 0xffffffffffffffffULL;
    }
}

// ---------------- per-edge geometry: sh, cut, rbf*cut ----------------
__global__ void __launch_bounds__(256) k_edges(const float* __restrict__ x) {
    int e = blockIdx.x * 256 + threadIdx.x;          // < BB*NN*KK = 262144
    int b  = e >> 15;                                 // NN*KK = 32768
    int nk = e & 32767;
    int n  = nk >> 5;
    int src = g_knn[e];
    const float* pos = x + (size_t)b * NN * 3;
    float vx = pos[n*3+0] - pos[src*3+0];
    float vy = pos[n*3+1] - pos[src*3+1];
    float vz = pos[n*3+2] - pos[src*3+2];
    float r = sqrtf(vx*vx + vy*vy + vz*vz);
    float inv = 1.f / fmaxf(r, 1e-9f);
    float ux = vx*inv, uy = vy*inv, uz = vz*inv;
    const float S3  = 1.7320508075688772f;
    const float S15 = 3.872983346207417f;
    const float S5  = 2.23606797749979f;
    float sh[9];
    sh[0] = 1.f;
    sh[1] = S3 * ux; sh[2] = S3 * uy; sh[3] = S3 * uz;
    sh[4] = S15 * ux * uy;
    sh[5] = S15 * uy * uz;
    sh[6] = 0.5f * S5 * (3.f * uz * uz - 1.f);
    sh[7] = S15 * ux * uz;
    sh[8] = 0.5f * S15 * (ux*ux - uy*uy);
#pragma unroll
    for (int s = 0; s < 9; s++) g_sh[(size_t)e * SHDD + s] = sh[s];
    float xx = 10.f * (1.f - 0.5f * r);
    float cut = (xx > 0.f) ? 1.4f * __expf(-1.f / xx) : 0.f;
    g_cut[e] = cut;
    const float step = 2.0f / 31.0f;
    const float fact = 4.7982245866230005f;   // sqrt(32)*0.95/1.12
    float fc = fact * cut;
    float rs = r / step;
#pragma unroll
    for (int i = 0; i < NBB; i++) {
        float d = rs - (float)i;
        g_rbf[(size_t)e * NBB + i] = __expf(-d*d) * fc;
    }
}

// ---------------- node embedding: [y, t] @ W_embed ----------------
__global__ void __launch_bounds__(256) k_embed(const float* __restrict__ y,
                                               const float* __restrict__ t,
                                               const float* __restrict__ W) {
    __shared__ float s_in[19];
    int bn = blockIdx.x, b = bn >> 10, tid = threadIdx.x;
    if (tid < 3) s_in[tid] = y[(size_t)bn * 3 + tid];
    else if (tid < 19) s_in[tid] = t[b * TD + tid - 3];
    __syncthreads();
    float acc = 0.f;
#pragma unroll
    for (int i = 0; i < 19; i++) acc += s_in[i] * W[i * DD + tid];
    g_node[0][(size_t)bn * DD + tid] = acc;
}

// ---------------- per-layer precompute: q, vsrc, P1/P2 fused; then m ----------------
__global__ void __launch_bounds__(256, 2) k_pre(int cur,
        const float* __restrict__ Wq, const float* __restrict__ Wv,
        const float* __restrict__ Wk1, const float* __restrict__ Wk2,
        const float* __restrict__ bk1, const float* __restrict__ t) {
    __shared__ float s_nd[16 * DD];
    __shared__ float s_q [16 * DD];
    int tid = threadIdx.x;
    int node0 = blockIdx.x * 16;
    int b = node0 >> 10;
    const float* nodein = g_node[cur];
    const float* np = nodein + (size_t)node0 * DD;
    for (int i = tid; i < 16 * DD; i += 256) s_nd[i] = np[i];
    __syncthreads();

    // fused q (col tid), vsrc (col tid), P1/P2 (col tid&127) — one pass over s_nd
    {
        float accq[16], accv[16], accp[16];
#pragma unroll
        for (int g = 0; g < 16; g++) { accq[g] = 0.f; accv[g] = 0.f; accp[g] = 0.f; }
        int j = tid & 127;
        const float* Wp = Wk1 + ((tid < 128) ? 48 : 176) * HIDD + j;
        for (int i = 0; i < 128; i += 4) {
            float q0 = Wq[(i+0)*DD + tid], q1 = Wq[(i+1)*DD + tid];
            float q2 = Wq[(i+2)*DD + tid], q3 = Wq[(i+3)*DD + tid];
            float v0 = Wv[(i+0)*DD + tid], v1 = Wv[(i+1)*DD + tid];
            float v2 = Wv[(i+2)*DD + tid], v3 = Wv[(i+3)*DD + tid];
            float p0 = Wp[(i+0)*HIDD],     p1 = Wp[(i+1)*HIDD];
            float p2 = Wp[(i+2)*HIDD],     p3 = Wp[(i+3)*HIDD];
#pragma unroll
            for (int g = 0; g < 16; g++) {
                float4 a = *(const float4*)&s_nd[g*DD + i];
                accq[g] += a.x*q0 + a.y*q1 + a.z*q2 + a.w*q3;
                accv[g] += a.x*v0 + a.y*v1 + a.z*v2 + a.w*v3;
                accp[g] += a.x*p0 + a.y*p1 + a.z*p2 + a.w*p3;
            }
        }
        for (int i = 128; i < 256; i += 4) {
            float q0 = Wq[(i+0)*DD + tid], q1 = Wq[(i+1)*DD + tid];
            float q2 = Wq[(i+2)*DD + tid], q3 = Wq[(i+3)*DD + tid];
            float v0 = Wv[(i+0)*DD + tid], v1 = Wv[(i+1)*DD + tid];
            float v2 = Wv[(i+2)*DD + tid], v3 = Wv[(i+3)*DD + tid];
#pragma unroll
            for (int g = 0; g < 16; g++) {
                float4 a = *(const float4*)&s_nd[g*DD + i];
                accq[g] += a.x*q0 + a.y*q1 + a.z*q2 + a.w*q3;
                accv[g] += a.x*v0 + a.y*v1 + a.z*v2 + a.w*v3;
            }
        }
#pragma unroll
        for (int g = 0; g < 16; g++) {
            s_q[g*DD + tid] = accq[g];
            g_vsrc[(size_t)(node0 + g) * DD + tid] = accv[g];
        }
        if (tid < 128) {
#pragma unroll
            for (int g = 0; g < 16; g++)
                g_P1[(size_t)(node0 + g) * HIDD + j] = accp[g];
        } else {
            float base = bk1[j];
#pragma unroll
            for (int ii = 0; ii < TD; ii++)
                base += t[b * TD + ii] * Wk1[(NBB + ii) * HIDD + j];
#pragma unroll
            for (int g = 0; g < 16; g++)
                g_P2[(size_t)(node0 + g) * HIDD + j] = accp[g] + base;
        }
    }
    __syncthreads();

    // m[j][hh] = sum_d Wk2[j, hh*32+d] * q[hh*32+d]
    {
        int j  = tid & 127;
        int hb = (tid >> 7) * 4;
        for (int hh = hb; hh < hb + 4; hh++) {
            const float* W = Wk2 + j * DD + hh * DHH;
            float4 w[8];
#pragma unroll
            for (int d8 = 0; d8 < 8; d8++) w[d8] = *(const float4*)&W[d8 * 4];
#pragma unroll
            for (int g = 0; g < 16; g++) {
                float s = 0.f;
#pragma unroll
                for (int d8 = 0; d8 < 8; d8++) {
                    float4 q = *(const float4*)&s_q[g*DD + hh*DHH + d8*4];
                    s += w[d8].x*q.x + w[d8].y*q.y + w[d8].z*q.z + w[d8].w*q.w;
                }
                g_m[((size_t)(node0 + g) * HIDD + j) * HH + hh] = s;
            }
        }
    }
}

// ---------------- edge MLP h + logits (2 nodes = 64 edges, 128 threads, 2 cols/thread) ----------------
__global__ void __launch_bounds__(128, 5) k_h(const float* __restrict__ Wk1l) {
    __shared__ float s_h[64 * HIDD];       // 32KB; first 8KB aliases rbf staging
    __shared__ float s_m2[2 * HIDD * HH];  // 8KB, layout [nd][hh][j]
    __shared__ int   s_src[64];
    float* s_rbf = s_h;                    // [64][32] (consumed before h is written)

    int tid = threadIdx.x;
    int node0 = blockIdx.x * 2;
    int b = node0 >> 10;
    size_t ebase = (size_t)node0 * KK;     // 64 edges

    for (int i = tid; i < 64 * NBB; i += 128) s_rbf[i] = g_rbf[ebase * NBB + i];
    // stage m transposed: s_m2[nd*1024 + hh*128 + j] = g_m[(node0+nd)*1024 + j*8 + hh]
    for (int i = tid; i < 2 * HIDD * HH; i += 128) {
        int nd = i >> 10, rem = i & 1023, hh = rem >> 7, jj = rem & 127;
        s_m2[i] = g_m[((size_t)(node0 + nd) * HIDD + jj) * HH + hh];
    }
    if (tid < 64) s_src[tid] = g_knn[ebase + tid];
    __syncthreads();

    int j0 = tid & 63, eh = tid >> 6;      // eh in {0,1}; cols j0 and j0+64
    float acc0[32], acc1[32];
#pragma unroll
    for (int e = 0; e < 32; e++) { acc0[e] = 0.f; acc1[e] = 0.f; }
#pragma unroll
    for (int i = 0; i < NBB; i += 4) {
        float wa0 = Wk1l[(i+0)*HIDD + j0],      wa1 = Wk1l[(i+1)*HIDD + j0];
        float wa2 = Wk1l[(i+2)*HIDD + j0],      wa3 = Wk1l[(i+3)*HIDD + j0];
        float wb0 = Wk1l[(i+0)*HIDD + j0 + 64], wb1 = Wk1l[(i+1)*HIDD + j0 + 64];
        float wb2 = Wk1l[(i+2)*HIDD + j0 + 64], wb3 = Wk1l[(i+3)*HIDD + j0 + 64];
#pragma unroll
        for (int e = 0; e < 32; e++) {
            float4 rb = *(const float4*)&s_rbf[(eh*32 + e)*NBB + i];
            acc0[e] += rb.x*wa0 + rb.y*wa1 + rb.z*wa2 + rb.w*wa3;
            acc1[e] += rb.x*wb0 + rb.y*wb1 + rb.z*wb2 + rb.w*wb3;
        }
    }
    float p2a = g_P2[(size_t)(node0 + eh) * HIDD + j0];
    float p2b = g_P2[(size_t)(node0 + eh) * HIDD + j0 + 64];
    const float* p1base = g_P1 + (size_t)(b * NN) * HIDD;
    __syncthreads();   // all rbf reads done before aliased h writes
#pragma unroll
    for (int e0 = 0; e0 < 32; e0 += 8) {
        float p1a[8], p1b[8];
#pragma unroll
        for (int u = 0; u < 8; u++) {
            size_t s = (size_t)s_src[eh*32 + e0 + u] * HIDD;
            p1a[u] = __ldg(&p1base[s + j0]);
            p1b[u] = __ldg(&p1base[s + j0 + 64]);
        }
#pragma unroll
        for (int u = 0; u < 8; u++) {
            int e = eh*32 + e0 + u;
            s_h[e*HIDD + j0]      = gelu_t(acc0[e0+u] + p1a[u] + p2a);
            s_h[e*HIDD + j0 + 64] = gelu_t(acc1[e0+u] + p1b[u] + p2b);
        }
    }
    __syncthreads();

    // logits: 512 outputs (64 e x 8 hh); thread -> fixed hh, 4 edges (m reused 4x)
    {
        int hh = tid & 7, eg = tid >> 3;   // eg in [0,16): edges eg*4..eg*4+3
        int e0 = eg * 4, nd = eg >> 3;
        const float* mm = &s_m2[nd * (HIDD*HH) + hh * HIDD];
        float s0 = 0.f, s1 = 0.f, s2 = 0.f, s3 = 0.f;
#pragma unroll 8
        for (int jj = 0; jj < HIDD; jj += 4) {
            float4 mv = *(const float4*)&mm[jj];
            float4 h0 = *(const float4*)&s_h[(e0+0)*HIDD + jj];
            float4 h1 = *(const float4*)&s_h[(e0+1)*HIDD + jj];
            float4 h2 = *(const float4*)&s_h[(e0+2)*HIDD + jj];
            float4 h3 = *(const float4*)&s_h[(e0+3)*HIDD + jj];
            s0 += h0.x*mv.x + h0.y*mv.y + h0.z*mv.z + h0.w*mv.w;
            s1 += h1.x*mv.x + h1.y*mv.y + h1.z*mv.z + h1.w*mv.w;
            s2 += h2.x*mv.x + h2.y*mv.y + h2.z*mv.z + h2.w*mv.w;
            s3 += h3.x*mv.x + h3.y*mv.y + h3.z*mv.z + h3.w*mv.w;
        }
        const float sc = 0.17677669529663687f;
        g_logit[(ebase + e0 + 0)*HH + hh] = s0 * sc;
        g_logit[(ebase + e0 + 1)*HH + hh] = s1 * sc;
        g_logit[(ebase + e0 + 2)*HH + hh] = s2 * sc;
        g_logit[(ebase + e0 + 3)*HH + hh] = s3 * sc;
    }
}

// ---------------- softmax + sh-contraction + gather-aggregate (1 node / block) ----------------
__global__ void __launch_bounds__(256) k_attn(const float* __restrict__ Wvl) {
    __shared__ float s_alpha[KK * HH];   // [k][hh]
    __shared__ float s_zsh[HH * SHDD];
    __shared__ float s_sh[KK * SHDD];
    __shared__ int   s_src[KK];

    int bn = blockIdx.x, b = bn >> 10, tid = threadIdx.x;
    int wp = tid >> 5, lane = tid & 31;  // wp = head, lane = k
    size_t ebase = (size_t)bn * KK;

    if (tid < KK) s_src[tid] = g_knn[ebase + tid];
    for (int i = tid; i < KK * SHDD; i += 256) s_sh[i] = g_sh[ebase * SHDD + i];

    float lg  = g_logit[(ebase + lane) * HH + wp];
    float cut = g_cut[ebase + lane];
    float mx = lg;
#pragma unroll
    for (int off = 16; off > 0; off >>= 1)
        mx = fmaxf(mx, __shfl_xor_sync(0xffffffffu, mx, off));
    float w = cut * __expf(lg - mx);
    float sum = w;
#pragma unroll
    for (int off = 16; off > 0; off >>= 1)
        sum += __shfl_xor_sync(0xffffffffu, sum, off);
    float alpha = w / (sum + 1e-9f);
    s_alpha[lane * HH + wp] = alpha;
    __syncthreads();

    // zsh[hh][s] = sum_k alpha * sh  (warp per head, shuffle reduce)
#pragma unroll
    for (int s = 0; s < SHDD; s++) {
        float v = alpha * s_sh[lane * SHDD + s];
#pragma unroll
        for (int off = 16; off > 0; off >>= 1)
            v += __shfl_xor_sync(0xffffffffu, v, off);
        if (lane == 0) s_zsh[wp * SHDD + s] = v;
    }
    __syncthreads();

    // agg[c] = sum_k alpha*vsrc[src] + sum_s zsh*Wv[256+s]
    {
        int c = tid, hh = tid >> 5;
        const float* vb = g_vsrc + (size_t)(b * NN) * DD;
        float a0 = 0.f, a1 = 0.f, a2 = 0.f, a3 = 0.f;
#pragma unroll
        for (int k = 0; k < KK; k += 4) {
            a0 += s_alpha[(k+0)*HH + hh] * __ldg(&vb[(size_t)s_src[k+0]*DD + c]);
            a1 += s_alpha[(k+1)*HH + hh] * __ldg(&vb[(size_t)s_src[k+1]*DD + c]);
            a2 += s_alpha[(k+2)*HH + hh] * __ldg(&vb[(size_t)s_src[k+2]*DD + c]);
            a3 += s_alpha[(k+3)*HH + hh] * __ldg(&vb[(size_t)s_src[k+3]*DD + c]);
        }
        float acc = (a0 + a1) + (a2 + a3);
#pragma unroll
        for (int s = 0; s < SHDD; s++)
            acc += s_zsh[hh * SHDD + s] * Wvl[(256 + s) * DD + c];
        g_agg[(size_t)bn * DD + c] = acc;
    }
}

// ---------------- output projection + scalar activation (128 threads, 2 cols/thread) ----------------
__global__ void __launch_bounds__(128, 6) k_proj(int cur, const float* __restrict__ Wo) {
    __shared__ float s_agg[16 * DD];
    int tid = threadIdx.x;
    int node0 = blockIdx.x * 16;
    const float* nodein = g_node[cur];
    float* nodeout = g_node[cur ^ 1];
    const float* ap = g_agg + (size_t)node0 * DD;
    for (int i = tid; i < 16 * DD; i += 128) s_agg[i] = ap[i];
    __syncthreads();
    int c0 = tid, c1 = tid + 128;
    float acc0[16], acc1[16];
#pragma unroll
    for (int g = 0; g < 16; g++) { acc0[g] = 0.f; acc1[g] = 0.f; }
    for (int i = 0; i < DD; i += 4) {
        float w0 = Wo[(i+0)*DD + c0], w1 = Wo[(i+1)*DD + c0];
        float w2 = Wo[(i+2)*DD + c0], w3 = Wo[(i+3)*DD + c0];
        float u0 = Wo[(i+0)*DD + c1], u1 = Wo[(i+1)*DD + c1];
        float u2 = Wo[(i+2)*DD + c1], u3 = Wo[(i+3)*DD + c1];
#pragma unroll
        for (int g = 0; g < 16; g++) {
            float4 a = *(const float4*)&s_agg[g*DD + i];
            acc0[g] += a.x*w0 + a.y*w1 + a.z*w2 + a.w*w3;
            acc1[g] += a.x*u0 + a.y*u1 + a.z*u2 + a.w*u3;
        }
    }
#pragma unroll
    for (int g = 0; g < 16; g++) {
        size_t base = (size_t)(node0 + g) * DD;
        float v0 = nodein[base + c0] + acc0[g];
        v0 = (tid < 64) ? gelu_t(v0) : tanh_f(v0);
        float v1 = nodein[base + c1] + acc1[g];   // cols 128..255: identity
        nodeout[base + c0] = v0;
        nodeout[base + c1] = v1;
    }
}

// ---------------- final projection agg @ Wo_out -> [B,N,3] ----------------
__global__ void __launch_bounds__(256) k_final(const float* __restrict__ Wo_out,
                                               float* __restrict__ out) {
    int gid = blockIdx.x * 256 + threadIdx.x;
    if (gid >= BB * NN * 3) return;
    int n = gid / 3, c = gid - n * 3;
    const float* ap = g_agg + (size_t)n * DD;
    float acc = 0.f;
#pragma unroll 4
    for (int i = 0; i < DD; i++) acc += ap[i] * Wo_out[i * 3 + c];
    out[gid] = acc;
}

// ---------------- launch ----------------
extern "C" void kernel_launch(void* const* d_in, const int* in_sizes, int n_in,
                              void* d_out, int out_size) {
    const float* x       = (const float*)d_in[0];
    const float* y       = (const float*)d_in[1];
    const float* t       = (const float*)d_in[2];
    const float* W_embed = (const float*)d_in[3];
    const float* Wk1     = (const float*)d_in[4];
    const float* bk1     = (const float*)d_in[5];
    const float* Wk2     = (const float*)d_in[6];
    const float* Wq      = (const float*)d_in[7];
    const float* Wv      = (const float*)d_in[8];
    const float* Wo      = (const float*)d_in[9];
    const float* Wo_out  = (const float*)d_in[10];
    float* out = (float*)d_out;

    k_knn  <<<BB*NN, 256>>>(x);
    k_edges<<<BB*NN*KK/256, 256>>>(x);
    k_embed<<<BB*NN, 256>>>(y, t, W_embed);

    for (int l = 0; l < 4; l++) {
        int cur = l & 1;
        const float* Wk1l = Wk1 + (size_t)l * 304 * HIDD;
        const float* Wvl  = Wv  + (size_t)l * 265 * DD;
        k_pre<<<BB*NN/16, 256>>>(cur,
                                 Wq + (size_t)l * DD * DD,
                                 Wvl, Wk1l,
                                 Wk2 + (size_t)l * HIDD * DD,
                                 bk1 + (size_t)l * HIDD,
                                 t);
        k_h   <<<BB*NN/2, 128>>>(Wk1l);
        k_attn<<<BB*NN, 256>>>(Wvl);
        if (l < 3) k_proj<<<BB*NN/16, 128>>>(cur, Wo + (size_t)l * DD * DD);
    }
    k_final<<<(BB*NN*3 + 255)/256, 256>>>(Wo_out, out);
}